// round 16
// baseline (speedup 1.0000x reference)
#include <cuda_runtime.h>
#include <cuda_bf16.h>
#include <math.h>
#include <cstdint>

#define NB 32
#define NT 1024
#define NE 256
#define NH 4
#define NHD 64
#define NP 32
#define NM (NB*NT)

// ---- scratch (static device globals; no runtime allocation) ----
__device__ float g_qkv[(size_t)NM*3*NE];
__device__ float g_ctx[(size_t)NM*NE];
__device__ float g_ao [(size_t)NM*NE];
__device__ float g_bs [NM];
__device__ int   g_pid[NM];
__device__ float g_pe [NB*NP*NE];
__device__ float g_wc [768*32];
__device__ float g_bc [768];
__device__ uint32_t g_khi[(size_t)NB*NH*NT*32];
__device__ uint32_t g_klo[(size_t)NB*NH*NT*32];
__device__ uint32_t g_vhi[(size_t)NB*NH*NT*32];
__device__ uint32_t g_vlo[(size_t)NB*NH*NT*32];

// ============================================================================
// helpers
// ============================================================================
__device__ __forceinline__ uint32_t cvta_s(const void* p) {
    return (uint32_t)__cvta_generic_to_shared(p);
}
__device__ __forceinline__ void split_pack_bf16(float x0, float x1,
                                                uint32_t& hi, uint32_t& lo) {
    uint32_t h;
    asm("cvt.rn.bf16x2.f32 %0, %1, %2;" : "=r"(h) : "f"(x1), "f"(x0));
    float h0 = __uint_as_float(h << 16);
    float h1 = __uint_as_float(h & 0xffff0000u);
    float l0 = x0 - h0;
    float l1 = x1 - h1;
    uint32_t l;
    asm("cvt.rn.bf16x2.f32 %0, %1, %2;" : "=r"(l) : "f"(l1), "f"(l0));
    hi = h; lo = l;
}
__device__ __forceinline__ void mma_bf16(float* d, const uint32_t* a, const uint32_t* b) {
    asm volatile(
        "mma.sync.aligned.m16n8k16.row.col.f32.bf16.bf16.f32 "
        "{%0,%1,%2,%3}, {%4,%5,%6,%7}, {%8,%9}, {%0,%1,%2,%3};"
        : "+f"(d[0]), "+f"(d[1]), "+f"(d[2]), "+f"(d[3])
        : "r"(a[0]), "r"(a[1]), "r"(a[2]), "r"(a[3]), "r"(b[0]), "r"(b[1]));
}
__device__ __forceinline__ void ldsm_x4(uint32_t* r, uint32_t a) {
    asm volatile("ldmatrix.sync.aligned.m8n8.x4.shared.b16 {%0,%1,%2,%3}, [%4];"
        : "=r"(r[0]), "=r"(r[1]), "=r"(r[2]), "=r"(r[3]) : "r"(a));
}
__device__ __forceinline__ void ldsm_x4_t(uint32_t* r, uint32_t a) {
    asm volatile("ldmatrix.sync.aligned.m8n8.x4.trans.shared.b16 {%0,%1,%2,%3}, [%4];"
        : "=r"(r[0]), "=r"(r[1]), "=r"(r[2]), "=r"(r[3]) : "r"(a));
}

// ============================================================================
// Fold input projection into qkv: Wc = Win @ Wip, bc = Win @ b_ip + b_in.
// ============================================================================
__global__ __launch_bounds__(32) void fold_kernel(
    const float* __restrict__ win, const float* __restrict__ ipw,
    const float* __restrict__ ipb, const float* __restrict__ inb,
    float* __restrict__ wc, float* __restrict__ bc)
{
    const int i = blockIdx.x;
    const int j = threadIdx.x;
    const float* wr = win + i*256;
    float acc = 0.f;
#pragma unroll 8
    for (int k = 0; k < 256; k++)
        acc += wr[k] * ipw[k*32 + j];
    wc[i*32 + j] = acc;
    float bacc = 0.f;
    for (int k = j; k < 256; k += 32)
        bacc += wr[k] * ipb[k];
#pragma unroll
    for (int off = 16; off; off >>= 1)
        bacc += __shfl_xor_sync(0xffffffffu, bacc, off);
    if (j == 0) bc[i] = bacc + inb[i];
}

// ============================================================================
// Pre-split K and V into packed bf16x2 hi/lo word arrays, [b][h][t][32w].
// ============================================================================
__global__ __launch_bounds__(256) void presplit_kernel(
    const float* __restrict__ qkv,
    uint32_t* __restrict__ khi, uint32_t* __restrict__ klo,
    uint32_t* __restrict__ vhi, uint32_t* __restrict__ vlo)
{
    const int n = blockIdx.x * 256 + threadIdx.x;
    const int r = n >> 5, inner = n & 31;
    const int kv = inner >> 4, h = (inner >> 2) & 3, dc = inner & 3;
    const float* src = qkv + (size_t)r*768 + 256 + kv*256 + h*64 + dc*16;
    const int b = r >> 10, t = r & 1023;
    uint32_t* dh = kv ? vhi : khi;
    uint32_t* dl = kv ? vlo : klo;
    const size_t off = ((size_t)((b*4 + h)*1024 + t))*32 + dc*8;
    uint32_t hw[8], lw[8];
#pragma unroll
    for (int i = 0; i < 4; i++) {
        float4 v = *(const float4*)(src + 4*i);
        split_pack_bf16(v.x, v.y, hw[2*i],   lw[2*i]);
        split_pack_bf16(v.z, v.w, hw[2*i+1], lw[2*i+1]);
    }
    *(uint4*)&dh[off]     = make_uint4(hw[0], hw[1], hw[2], hw[3]);
    *(uint4*)&dh[off + 4] = make_uint4(hw[4], hw[5], hw[6], hw[7]);
    *(uint4*)&dl[off]     = make_uint4(lw[0], lw[1], lw[2], lw[3]);
    *(uint4*)&dl[off + 4] = make_uint4(lw[4], lw[5], lw[6], lw[7]);
}

// ============================================================================
// C[M,N] = A[M,K] @ W[N,K]^T + bias, bf16x3 GEMM + ldmatrix.
// ============================================================================
__global__ __launch_bounds__(256) void gemm_mma_kernel(
    const float* __restrict__ A, const float* __restrict__ W,
    const float* __restrict__ bias, float* __restrict__ C,
    int Ndim, int Kdim)
{
    __shared__ uint32_t sAhi[128*12], sAlo[128*12];
    __shared__ uint32_t sBhi[128*12], sBlo[128*12];

    const int tid  = threadIdx.x;
    const int wid  = tid >> 5;
    const int lane = tid & 31;
    const int g    = lane >> 2;
    const int tig  = lane & 3;
    const int wm   = wid >> 2;
    const int wn   = wid & 3;
    const int bm   = blockIdx.y << 7;
    const int bn   = blockIdx.x << 7;

    float c[4][4][4];
#pragma unroll
    for (int mi = 0; mi < 4; mi++)
#pragma unroll
        for (int nj = 0; nj < 4; nj++)
#pragma unroll
            for (int r = 0; r < 4; r++) c[mi][nj][r] = 0.f;

    const int row  = tid >> 1;
    const int half = tid & 1;
    const float* Ap = A + (size_t)(bm + row) * Kdim + half*8;
    const float* Wp = W + (size_t)(bn + row) * Kdim + half*8;
    const int sbase = row*12 + half*4;

    const uint32_t sAhiB = cvta_s(sAhi), sAloB = cvta_s(sAlo);
    const uint32_t sBhiB = cvta_s(sBhi), sBloB = cvta_s(sBlo);
    const int t8  = lane & 7;
    const int sel = lane >> 3;
    const uint32_t afrag = (uint32_t)((((lane & 15) + wm*64)*12 + (lane >> 4)*4) * 4);
    const uint32_t bfrag = (uint32_t)(((wn*32 + (sel >> 1)*8 + t8)*12 + (sel & 1)*4) * 4);

    const int nch = Kdim >> 4;
    for (int ch = 0; ch < nch; ch++) {
        const int k0 = ch << 4;
        __syncthreads();
        {
            float4 a0 = *(const float4*)(Ap + k0);
            float4 a1 = *(const float4*)(Ap + k0 + 4);
            float4 b0 = *(const float4*)(Wp + k0);
            float4 b1 = *(const float4*)(Wp + k0 + 4);
            split_pack_bf16(a0.x, a0.y, sAhi[sbase+0], sAlo[sbase+0]);
            split_pack_bf16(a0.z, a0.w, sAhi[sbase+1], sAlo[sbase+1]);
            split_pack_bf16(a1.x, a1.y, sAhi[sbase+2], sAlo[sbase+2]);
            split_pack_bf16(a1.z, a1.w, sAhi[sbase+3], sAlo[sbase+3]);
            split_pack_bf16(b0.x, b0.y, sBhi[sbase+0], sBlo[sbase+0]);
            split_pack_bf16(b0.z, b0.w, sBhi[sbase+1], sBlo[sbase+1]);
            split_pack_bf16(b1.x, b1.y, sBhi[sbase+2], sBlo[sbase+2]);
            split_pack_bf16(b1.z, b1.w, sBhi[sbase+3], sBlo[sbase+3]);
        }
        __syncthreads();

        uint32_t ahi[4][4], alo[4][4];
#pragma unroll
        for (int mi = 0; mi < 4; mi++) {
            ldsm_x4(ahi[mi], sAhiB + afrag + mi*768);
            ldsm_x4(alo[mi], sAloB + afrag + mi*768);
        }
        uint32_t bhi[8], blo[8];
        ldsm_x4(bhi + 0, sBhiB + bfrag);
        ldsm_x4(bhi + 4, sBhiB + bfrag + 768);
        ldsm_x4(blo + 0, sBloB + bfrag);
        ldsm_x4(blo + 4, sBloB + bfrag + 768);

#pragma unroll
        for (int mi = 0; mi < 4; mi++)
#pragma unroll
            for (int nj = 0; nj < 4; nj++)
                mma_bf16(c[mi][nj], ahi[mi], bhi + 2*nj);
#pragma unroll
        for (int mi = 0; mi < 4; mi++)
#pragma unroll
            for (int nj = 0; nj < 4; nj++)
                mma_bf16(c[mi][nj], ahi[mi], blo + 2*nj);
#pragma unroll
        for (int mi = 0; mi < 4; mi++)
#pragma unroll
            for (int nj = 0; nj < 4; nj++)
                mma_bf16(c[mi][nj], alo[mi], bhi + 2*nj);
    }

#pragma unroll
    for (int mi = 0; mi < 4; mi++) {
#pragma unroll
        for (int nj = 0; nj < 4; nj++) {
            const int cc = bn + wn*32 + nj*8 + 2*tig;
            const int r0 = bm + wm*64 + mi*16 + g;
            float2 bb = *(const float2*)(bias + cc);
            *(float2*)(C + (size_t)r0 * Ndim + cc) =
                make_float2(c[mi][nj][0] + bb.x, c[mi][nj][1] + bb.y);
            *(float2*)(C + (size_t)(r0 + 8) * Ndim + cc) =
                make_float2(c[mi][nj][2] + bb.x, c[mi][nj][3] + bb.y);
        }
    }
}

// ============================================================================
// Flash attention, bf16x3 m16n8k16 + ldmatrix, BQ=128 (8 warps),
// DOUBLE-BUFFERED K/V tiles (one sync/iter; next tile's LDG+STS overlap
// current compute). P built in registers (no smem round-trip).
// ============================================================================
__global__ __launch_bounds__(256) void flash_mma_kernel(
    const float* __restrict__ qkv,
    const uint32_t* __restrict__ khi, const uint32_t* __restrict__ klo,
    const uint32_t* __restrict__ vhi, const uint32_t* __restrict__ vlo,
    float* __restrict__ ctx)
{
    __shared__ uint32_t sKhi[2][32*36], sKlo[2][32*36];
    __shared__ uint32_t sVhi[2][32*36], sVlo[2][32*36];

    const int tid  = threadIdx.x;
    const int w    = tid >> 5;
    const int lane = tid & 31;
    const int g    = lane >> 2;
    const int tig  = lane & 3;

    const int qb = blockIdx.x;
    const int bh = blockIdx.y;
    const int b  = bh >> 2, h = bh & 3;

    const float* base = qkv + (size_t)b * NT * (3*NE);
    const int qoff = h * NHD;
    const int qstart = qb << 7;

    uint32_t qhi[4][4], qlo[4][4];
    {
        const float* r0p = base + (size_t)(qstart + 16*w + g) * (3*NE) + qoff;
        const float* r1p = base + (size_t)(qstart + 16*w + g + 8) * (3*NE) + qoff;
#pragma unroll
        for (int kf = 0; kf < 4; kf++) {
            float2 v00 = *(const float2*)(r0p + 16*kf + 2*tig);
            float2 v10 = *(const float2*)(r1p + 16*kf + 2*tig);
            float2 v01 = *(const float2*)(r0p + 16*kf + 2*tig + 8);
            float2 v11 = *(const float2*)(r1p + 16*kf + 2*tig + 8);
            split_pack_bf16(v00.x*0.125f, v00.y*0.125f, qhi[kf][0], qlo[kf][0]);
            split_pack_bf16(v10.x*0.125f, v10.y*0.125f, qhi[kf][1], qlo[kf][1]);
            split_pack_bf16(v01.x*0.125f, v01.y*0.125f, qhi[kf][2], qlo[kf][2]);
            split_pack_bf16(v11.x*0.125f, v11.y*0.125f, qhi[kf][3], qlo[kf][3]);
        }
    }

    float o[8][4];
#pragma unroll
    for (int j = 0; j < 8; j++)
#pragma unroll
        for (int r = 0; r < 4; r++) o[j][r] = 0.f;
    float l0 = 0.f, l1 = 0.f;

    const int fr = tid >> 3;
    const int fc = (tid & 7) * 4;
    const int so = fr*36 + fc;
    const size_t gbase = (size_t)((b*4 + h)*1024) * 32;

    const int t8  = lane & 7;
    const int sel = lane >> 3;
    const uint32_t kfrag = (uint32_t)((((sel >> 1)*8 + t8)*36 + (sel & 1)*4) * 4);
    const uint32_t vfrag = (uint32_t)((((sel & 1)*8 + t8)*36 + (sel >> 1)*4) * 4);

    // preload tile 0 into buffer 0
    {
        const size_t go = gbase + (size_t)fr*32 + fc;
        *(uint4*)&sKhi[0][so] = *(const uint4*)&khi[go];
        *(uint4*)&sKlo[0][so] = *(const uint4*)&klo[go];
        *(uint4*)&sVhi[0][so] = *(const uint4*)&vhi[go];
        *(uint4*)&sVlo[0][so] = *(const uint4*)&vlo[go];
    }

    for (int kb = 0; kb < 32; kb++) {
        const int cur = kb & 1;
        __syncthreads();   // buf[cur] stores visible; buf[1-cur] readers done
        if (kb < 31) {
            const size_t go = gbase + (size_t)((kb+1)*32 + fr)*32 + fc;
            *(uint4*)&sKhi[1-cur][so] = *(const uint4*)&khi[go];
            *(uint4*)&sKlo[1-cur][so] = *(const uint4*)&klo[go];
            *(uint4*)&sVhi[1-cur][so] = *(const uint4*)&vhi[go];
            *(uint4*)&sVlo[1-cur][so] = *(const uint4*)&vlo[go];
        }
        const uint32_t sKhiB = cvta_s(sKhi[cur]), sKloB = cvta_s(sKlo[cur]);
        const uint32_t sVhiB = cvta_s(sVhi[cur]), sVloB = cvta_s(sVlo[cur]);

        // ---- S = Q K^T with split hi/err accumulators ----
        float s_hi[4][4], s_er[4][4];
#pragma unroll
        for (int j = 0; j < 4; j++)
#pragma unroll
            for (int r = 0; r < 4; r++) { s_hi[j][r] = 0.f; s_er[j][r] = 0.f; }
#pragma unroll
        for (int kf = 0; kf < 4; kf++) {
            uint32_t bh8[8], bl8[8];
            ldsm_x4(bh8 + 0, sKhiB + kfrag + kf*32);
            ldsm_x4(bh8 + 4, sKhiB + kfrag + 2304 + kf*32);
            ldsm_x4(bl8 + 0, sKloB + kfrag + kf*32);
            ldsm_x4(bl8 + 4, sKloB + kfrag + 2304 + kf*32);
#pragma unroll
            for (int j = 0; j < 4; j++) mma_bf16(s_hi[j], qhi[kf], bh8 + 2*j);
#pragma unroll
            for (int j = 0; j < 4; j++) mma_bf16(s_er[j], qhi[kf], bl8 + 2*j);
#pragma unroll
            for (int j = 0; j < 4; j++) mma_bf16(s_er[j], qlo[kf], bh8 + 2*j);
        }

        // ---- softmax weights p = exp(s) (no max shift) ----
        float p[4][4];
        float sum0 = 0.f, sum1 = 0.f;
#pragma unroll
        for (int j = 0; j < 4; j++) {
            p[j][0] = __expf(s_hi[j][0] + s_er[j][0]);
            p[j][1] = __expf(s_hi[j][1] + s_er[j][1]);
            p[j][2] = __expf(s_hi[j][2] + s_er[j][2]);
            p[j][3] = __expf(s_hi[j][3] + s_er[j][3]);
            sum0 += p[j][0] + p[j][1];
            sum1 += p[j][2] + p[j][3];
        }
        sum0 += __shfl_xor_sync(0xffffffffu, sum0, 1);
        sum0 += __shfl_xor_sync(0xffffffffu, sum0, 2);
        sum1 += __shfl_xor_sync(0xffffffffu, sum1, 1);
        sum1 += __shfl_xor_sync(0xffffffffu, sum1, 2);
        l0 += sum0;
        l1 += sum1;

        // ---- O += P V : P A-fragments built directly in registers ----
#pragma unroll
        for (int kf = 0; kf < 2; kf++) {
            uint32_t ph[4], pl[4];
            split_pack_bf16(p[2*kf  ][0], p[2*kf  ][1], ph[0], pl[0]);
            split_pack_bf16(p[2*kf  ][2], p[2*kf  ][3], ph[1], pl[1]);
            split_pack_bf16(p[2*kf+1][0], p[2*kf+1][1], ph[2], pl[2]);
            split_pack_bf16(p[2*kf+1][2], p[2*kf+1][3], ph[3], pl[3]);
#pragma unroll
            for (int j0 = 0; j0 < 8; j0 += 2) {
                uint32_t vh4[4], vl4[4];
                ldsm_x4_t(vh4, sVhiB + vfrag + kf*2304 + j0*16);
                ldsm_x4_t(vl4, sVloB + vfrag + kf*2304 + j0*16);
                mma_bf16(o[j0],   ph, vh4 + 0);
                mma_bf16(o[j0+1], ph, vh4 + 2);
                mma_bf16(o[j0],   ph, vl4 + 0);
                mma_bf16(o[j0+1], ph, vl4 + 2);
                mma_bf16(o[j0],   pl, vh4 + 0);
                mma_bf16(o[j0+1], pl, vh4 + 2);
            }
        }
    }

    const float inv0 = 1.f / l0, inv1 = 1.f / l1;
    float* c0 = ctx + ((size_t)(b*NT) + qstart + 16*w + g    ) * NE + h*NHD;
    float* c1 = ctx + ((size_t)(b*NT) + qstart + 16*w + g + 8) * NE + h*NHD;
#pragma unroll
    for (int j = 0; j < 8; j++) {
        *(float2*)(c0 + 8*j + 2*tig) = make_float2(o[j][0]*inv0, o[j][1]*inv0);
        *(float2*)(c1 + 8*j + 2*tig) = make_float2(o[j][2]*inv1, o[j][3]*inv1);
    }
}

// ============================================================================
// Boundary MLP: one warp per row, lane = hidden unit.
// ============================================================================
__global__ __launch_bounds__(256) void boundary_kernel(
    const float* __restrict__ ao, const float* __restrict__ w1,
    const float* __restrict__ b1, const float* __restrict__ w2,
    const float* __restrict__ b2, float* __restrict__ bscore)
{
    int row  = (blockIdx.x << 3) + (threadIdx.x >> 5);
    int lane = threadIdx.x & 31;
    const float4* a = (const float4*)(ao + (size_t)row * NE);
    const float4* w = (const float4*)(w1 + lane * NE);
    float acc = 0.f;
#pragma unroll 16
    for (int d = 0; d < 64; d++) {
        float4 av = a[d], wv = w[d];
        acc += av.x*wv.x + av.y*wv.y + av.z*wv.z + av.w*wv.w;
    }
    float hh = fmaxf(acc + b1[lane], 0.f);
    float s = hh * w2[lane];
#pragma unroll
    for (int off = 16; off; off >>= 1)
        s += __shfl_xor_sync(0xffffffffu, s, off);
    if (lane == 0)
        bscore[row] = 1.f / (1.f + expf(-(s + b2[0])));
}

// ============================================================================
// Per-batch inclusive cumsum (double) -> normalized -> patch ids.
// ============================================================================
__global__ __launch_bounds__(1024) void scan_kernel(
    const float* __restrict__ bscore, int* __restrict__ pid)
{
    __shared__ double sa[1024], sb[1024];
    int b = blockIdx.x, t = threadIdx.x;
    sa[t] = (double)bscore[b*NT + t];
    __syncthreads();
    double* src = sa; double* dst = sb;
#pragma unroll
    for (int off = 1; off < 1024; off <<= 1) {
        double v = src[t];
        if (t >= off) v += src[t - off];
        dst[t] = v;
        __syncthreads();
        double* tmp = src; src = dst; dst = tmp;
    }
    double total = src[1023] + 1e-6;
    double cbp = src[t] / total;
    int p = (int)floor(cbp * (double)NP);
    if (p > NP-1) p = NP-1;
    if (p < 0) p = 0;
    pid[b*NT + t] = p;
}

__device__ __forceinline__ int lower_bound_dev(const int* a, int n, int key) {
    int lo = 0, hi = n;
    while (lo < hi) { int mid = (lo + hi) >> 1; if (a[mid] < key) lo = mid + 1; else hi = mid; }
    return lo;
}

// ============================================================================
// Segment-mean pooling; pid monotone -> contiguous ranges, no atomics.
// ============================================================================
__global__ __launch_bounds__(256) void pool_kernel(
    const float* __restrict__ ao, const int* __restrict__ pid,
    float* __restrict__ pe)
{
    int bp = blockIdx.x;
    int b = bp >> 5, p = bp & 31;
    const int* pa = pid + b*NT;
    int s = lower_bound_dev(pa, NT, p);
    int e = lower_bound_dev(pa, NT, p+1);
    float inv = 1.f / (float)((e - s) > 0 ? (e - s) : 1);
    int col = threadIdx.x;
    float sum = 0.f;
    for (int t = s; t < e; t++)
        sum += ao[((size_t)(b*NT) + t) * NE + col];
    pe[(size_t)bp * NE + col] = sum * inv;
}

// ============================================================================
extern "C" void kernel_launch(void* const* d_in, const int* in_sizes, int n_in,
                              void* d_out, int out_size)
{
    (void)in_sizes; (void)n_in; (void)out_size;
    const float* x        = (const float*)d_in[0];
    const float* ip_w     = (const float*)d_in[1];
    const float* ip_b     = (const float*)d_in[2];
    const float* inproj_w = (const float*)d_in[3];
    const float* inproj_b = (const float*)d_in[4];
    const float* out_w    = (const float*)d_in[5];
    const float* out_b    = (const float*)d_in[6];
    const float* bp_w1    = (const float*)d_in[7];
    const float* bp_b1    = (const float*)d_in[8];
    const float* bp_w2    = (const float*)d_in[9];
    const float* bp_b2    = (const float*)d_in[10];
    const float* pr_w     = (const float*)d_in[11];
    const float* pr_b     = (const float*)d_in[12];
    float* out = (float*)d_out;

    void* p;
    float *qkv, *ctx, *ao, *bs, *pe, *wc, *bc; int* pid;
    uint32_t *khi, *klo, *vhi, *vlo;
    cudaGetSymbolAddress(&p, g_qkv); qkv = (float*)p;
    cudaGetSymbolAddress(&p, g_ctx); ctx = (float*)p;
    cudaGetSymbolAddress(&p, g_ao);  ao  = (float*)p;
    cudaGetSymbolAddress(&p, g_bs);  bs  = (float*)p;
    cudaGetSymbolAddress(&p, g_pid); pid = (int*)p;
    cudaGetSymbolAddress(&p, g_pe);  pe  = (float*)p;
    cudaGetSymbolAddress(&p, g_wc);  wc  = (float*)p;
    cudaGetSymbolAddress(&p, g_bc);  bc  = (float*)p;
    cudaGetSymbolAddress(&p, g_khi); khi = (uint32_t*)p;
    cudaGetSymbolAddress(&p, g_klo); klo = (uint32_t*)p;
    cudaGetSymbolAddress(&p, g_vhi); vhi = (uint32_t*)p;
    cudaGetSymbolAddress(&p, g_vlo); vlo = (uint32_t*)p;

    dim3 blk(256);
    // 0) fold ip into qkv
    fold_kernel<<<768, 32>>>(inproj_w, ip_w, ip_b, inproj_b, wc, bc);
    // 1) fused qkv projection (K=32)
    gemm_mma_kernel<<<dim3(3*NE/128, NM/128), blk>>>(x, wc, bc, qkv, 3*NE, 32);
    // 2) pre-split K/V
    presplit_kernel<<<4096, blk>>>(qkv, khi, klo, vhi, vlo);
    // 3) attention (BQ=128, double-buffered)
    flash_mma_kernel<<<dim3(NT/128, NB*NH), blk>>>(qkv, khi, klo, vhi, vlo, ctx);
    // 4) out projection
    gemm_mma_kernel<<<dim3(NE/128, NM/128), blk>>>(ctx, out_w, out_b, ao, NE, NE);
    // 5) boundary scores
    boundary_kernel<<<NM/8, blk>>>(ao, bp_w1, bp_b1, bp_w2, bp_b2, bs);
    // 6) cumsum + patch ids
    scan_kernel<<<NB, NT>>>(bs, pid);
    // 7) segment-mean pooling
    pool_kernel<<<NB*NP, NE>>>(ao, pid, pe);
    // 8) patch projection
    gemm_mma_kernel<<<dim3(NE/128, (NB*NP)/128), blk>>>(pe, pr_w, pr_b, out, NE, NE);
}

// round 17
// speedup vs baseline: 1.1658x; 1.1658x over previous
#include <cuda_runtime.h>
#include <cuda_bf16.h>
#include <math.h>
#include <cstdint>

#define NB 32
#define NT 1024
#define NE 256
#define NH 4
#define NHD 64
#define NP 32
#define NM (NB*NT)

// ---- scratch (static device globals; no runtime allocation) ----
__device__ float g_qkv[(size_t)NM*3*NE];
__device__ float g_ctx[(size_t)NM*NE];
__device__ float g_ao [(size_t)NM*NE];
__device__ float g_bs [NM];
__device__ int   g_pid[NM];
__device__ float g_pe [NB*NP*NE];
__device__ float g_wc [768*32];
__device__ float g_bc [768];
__device__ uint32_t g_khi[(size_t)NB*NH*NT*32];
__device__ uint32_t g_klo[(size_t)NB*NH*NT*32];
__device__ uint32_t g_vhi[(size_t)NB*NH*NT*32];
__device__ uint32_t g_vlo[(size_t)NB*NH*NT*32];

// ============================================================================
// helpers
// ============================================================================
__device__ __forceinline__ uint32_t cvta_s(const void* p) {
    return (uint32_t)__cvta_generic_to_shared(p);
}
__device__ __forceinline__ void split_pack_bf16(float x0, float x1,
                                                uint32_t& hi, uint32_t& lo) {
    uint32_t h;
    asm("cvt.rn.bf16x2.f32 %0, %1, %2;" : "=r"(h) : "f"(x1), "f"(x0));
    float h0 = __uint_as_float(h << 16);
    float h1 = __uint_as_float(h & 0xffff0000u);
    float l0 = x0 - h0;
    float l1 = x1 - h1;
    uint32_t l;
    asm("cvt.rn.bf16x2.f32 %0, %1, %2;" : "=r"(l) : "f"(l1), "f"(l0));
    hi = h; lo = l;
}
__device__ __forceinline__ void mma_bf16(float* d, const uint32_t* a, const uint32_t* b) {
    asm volatile(
        "mma.sync.aligned.m16n8k16.row.col.f32.bf16.bf16.f32 "
        "{%0,%1,%2,%3}, {%4,%5,%6,%7}, {%8,%9}, {%0,%1,%2,%3};"
        : "+f"(d[0]), "+f"(d[1]), "+f"(d[2]), "+f"(d[3])
        : "r"(a[0]), "r"(a[1]), "r"(a[2]), "r"(a[3]), "r"(b[0]), "r"(b[1]));
}
__device__ __forceinline__ void ldsm_x4(uint32_t* r, uint32_t a) {
    asm volatile("ldmatrix.sync.aligned.m8n8.x4.shared.b16 {%0,%1,%2,%3}, [%4];"
        : "=r"(r[0]), "=r"(r[1]), "=r"(r[2]), "=r"(r[3]) : "r"(a));
}
__device__ __forceinline__ void ldsm_x4_t(uint32_t* r, uint32_t a) {
    asm volatile("ldmatrix.sync.aligned.m8n8.x4.trans.shared.b16 {%0,%1,%2,%3}, [%4];"
        : "=r"(r[0]), "=r"(r[1]), "=r"(r[2]), "=r"(r[3]) : "r"(a));
}

// ============================================================================
// Fold input projection into qkv: Wc = Win @ Wip, bc = Win @ b_ip + b_in.
// ============================================================================
__global__ __launch_bounds__(32) void fold_kernel(
    const float* __restrict__ win, const float* __restrict__ ipw,
    const float* __restrict__ ipb, const float* __restrict__ inb,
    float* __restrict__ wc, float* __restrict__ bc)
{
    const int i = blockIdx.x;
    const int j = threadIdx.x;
    const float* wr = win + i*256;
    float acc = 0.f;
#pragma unroll 8
    for (int k = 0; k < 256; k++)
        acc += wr[k] * ipw[k*32 + j];
    wc[i*32 + j] = acc;
    float bacc = 0.f;
    for (int k = j; k < 256; k += 32)
        bacc += wr[k] * ipb[k];
#pragma unroll
    for (int off = 16; off; off >>= 1)
        bacc += __shfl_xor_sync(0xffffffffu, bacc, off);
    if (j == 0) bc[i] = bacc + inb[i];
}

// ============================================================================
// Pre-split K and V into packed bf16x2 hi/lo word arrays, [b][h][t][32w].
// ============================================================================
__global__ __launch_bounds__(256) void presplit_kernel(
    const float* __restrict__ qkv,
    uint32_t* __restrict__ khi, uint32_t* __restrict__ klo,
    uint32_t* __restrict__ vhi, uint32_t* __restrict__ vlo)
{
    const int n = blockIdx.x * 256 + threadIdx.x;
    const int r = n >> 5, inner = n & 31;
    const int kv = inner >> 4, h = (inner >> 2) & 3, dc = inner & 3;
    const float* src = qkv + (size_t)r*768 + 256 + kv*256 + h*64 + dc*16;
    const int b = r >> 10, t = r & 1023;
    uint32_t* dh = kv ? vhi : khi;
    uint32_t* dl = kv ? vlo : klo;
    const size_t off = ((size_t)((b*4 + h)*1024 + t))*32 + dc*8;
    uint32_t hw[8], lw[8];
#pragma unroll
    for (int i = 0; i < 4; i++) {
        float4 v = *(const float4*)(src + 4*i);
        split_pack_bf16(v.x, v.y, hw[2*i],   lw[2*i]);
        split_pack_bf16(v.z, v.w, hw[2*i+1], lw[2*i+1]);
    }
    *(uint4*)&dh[off]     = make_uint4(hw[0], hw[1], hw[2], hw[3]);
    *(uint4*)&dh[off + 4] = make_uint4(hw[4], hw[5], hw[6], hw[7]);
    *(uint4*)&dl[off]     = make_uint4(lw[0], lw[1], lw[2], lw[3]);
    *(uint4*)&dl[off + 4] = make_uint4(lw[4], lw[5], lw[6], lw[7]);
}

// ============================================================================
// C[M,N] = A[M,K] @ W[N,K]^T + bias, bf16x3 GEMM + ldmatrix.
// ============================================================================
__global__ __launch_bounds__(256) void gemm_mma_kernel(
    const float* __restrict__ A, const float* __restrict__ W,
    const float* __restrict__ bias, float* __restrict__ C,
    int Ndim, int Kdim)
{
    __shared__ uint32_t sAhi[128*12], sAlo[128*12];
    __shared__ uint32_t sBhi[128*12], sBlo[128*12];

    const int tid  = threadIdx.x;
    const int wid  = tid >> 5;
    const int lane = tid & 31;
    const int g    = lane >> 2;
    const int tig  = lane & 3;
    const int wm   = wid >> 2;
    const int wn   = wid & 3;
    const int bm   = blockIdx.y << 7;
    const int bn   = blockIdx.x << 7;

    float c[4][4][4];
#pragma unroll
    for (int mi = 0; mi < 4; mi++)
#pragma unroll
        for (int nj = 0; nj < 4; nj++)
#pragma unroll
            for (int r = 0; r < 4; r++) c[mi][nj][r] = 0.f;

    const int row  = tid >> 1;
    const int half = tid & 1;
    const float* Ap = A + (size_t)(bm + row) * Kdim + half*8;
    const float* Wp = W + (size_t)(bn + row) * Kdim + half*8;
    const int sbase = row*12 + half*4;

    const uint32_t sAhiB = cvta_s(sAhi), sAloB = cvta_s(sAlo);
    const uint32_t sBhiB = cvta_s(sBhi), sBloB = cvta_s(sBlo);
    const int t8  = lane & 7;
    const int sel = lane >> 3;
    const uint32_t afrag = (uint32_t)((((lane & 15) + wm*64)*12 + (lane >> 4)*4) * 4);
    const uint32_t bfrag = (uint32_t)(((wn*32 + (sel >> 1)*8 + t8)*12 + (sel & 1)*4) * 4);

    const int nch = Kdim >> 4;
    for (int ch = 0; ch < nch; ch++) {
        const int k0 = ch << 4;
        __syncthreads();
        {
            float4 a0 = *(const float4*)(Ap + k0);
            float4 a1 = *(const float4*)(Ap + k0 + 4);
            float4 b0 = *(const float4*)(Wp + k0);
            float4 b1 = *(const float4*)(Wp + k0 + 4);
            split_pack_bf16(a0.x, a0.y, sAhi[sbase+0], sAlo[sbase+0]);
            split_pack_bf16(a0.z, a0.w, sAhi[sbase+1], sAlo[sbase+1]);
            split_pack_bf16(a1.x, a1.y, sAhi[sbase+2], sAlo[sbase+2]);
            split_pack_bf16(a1.z, a1.w, sAhi[sbase+3], sAlo[sbase+3]);
            split_pack_bf16(b0.x, b0.y, sBhi[sbase+0], sBlo[sbase+0]);
            split_pack_bf16(b0.z, b0.w, sBhi[sbase+1], sBlo[sbase+1]);
            split_pack_bf16(b1.x, b1.y, sBhi[sbase+2], sBlo[sbase+2]);
            split_pack_bf16(b1.z, b1.w, sBhi[sbase+3], sBlo[sbase+3]);
        }
        __syncthreads();

        uint32_t ahi[4][4], alo[4][4];
#pragma unroll
        for (int mi = 0; mi < 4; mi++) {
            ldsm_x4(ahi[mi], sAhiB + afrag + mi*768);
            ldsm_x4(alo[mi], sAloB + afrag + mi*768);
        }
        uint32_t bhi[8], blo[8];
        ldsm_x4(bhi + 0, sBhiB + bfrag);
        ldsm_x4(bhi + 4, sBhiB + bfrag + 768);
        ldsm_x4(blo + 0, sBloB + bfrag);
        ldsm_x4(blo + 4, sBloB + bfrag + 768);

#pragma unroll
        for (int mi = 0; mi < 4; mi++)
#pragma unroll
            for (int nj = 0; nj < 4; nj++)
                mma_bf16(c[mi][nj], ahi[mi], bhi + 2*nj);
#pragma unroll
        for (int mi = 0; mi < 4; mi++)
#pragma unroll
            for (int nj = 0; nj < 4; nj++)
                mma_bf16(c[mi][nj], ahi[mi], blo + 2*nj);
#pragma unroll
        for (int mi = 0; mi < 4; mi++)
#pragma unroll
            for (int nj = 0; nj < 4; nj++)
                mma_bf16(c[mi][nj], alo[mi], bhi + 2*nj);
    }

#pragma unroll
    for (int mi = 0; mi < 4; mi++) {
#pragma unroll
        for (int nj = 0; nj < 4; nj++) {
            const int cc = bn + wn*32 + nj*8 + 2*tig;
            const int r0 = bm + wm*64 + mi*16 + g;
            float2 bb = *(const float2*)(bias + cc);
            *(float2*)(C + (size_t)r0 * Ndim + cc) =
                make_float2(c[mi][nj][0] + bb.x, c[mi][nj][1] + bb.y);
            *(float2*)(C + (size_t)(r0 + 8) * Ndim + cc) =
                make_float2(c[mi][nj][2] + bb.x, c[mi][nj][3] + bb.y);
        }
    }
}

// ============================================================================
// Flash attention, bf16x3 m16n8k16 + ldmatrix, BQ=128 (8 warps),
// DOUBLE-BUFFERED K/V tiles with __launch_bounds__(256,2) forcing regs<=128
// (R16's regression was 130 regs -> 1 CTA/SM; cap restores 2 CTAs).
// P built in registers (no smem round-trip).
// ============================================================================
__global__ __launch_bounds__(256, 2) void flash_mma_kernel(
    const float* __restrict__ qkv,
    const uint32_t* __restrict__ khi, const uint32_t* __restrict__ klo,
    const uint32_t* __restrict__ vhi, const uint32_t* __restrict__ vlo,
    float* __restrict__ ctx)
{
    __shared__ uint32_t sKhi[2][32*36], sKlo[2][32*36];
    __shared__ uint32_t sVhi[2][32*36], sVlo[2][32*36];

    const int tid  = threadIdx.x;
    const int w    = tid >> 5;
    const int lane = tid & 31;
    const int g    = lane >> 2;
    const int tig  = lane & 3;

    const int qb = blockIdx.x;
    const int bh = blockIdx.y;
    const int b  = bh >> 2, h = bh & 3;

    const float* base = qkv + (size_t)b * NT * (3*NE);
    const int qoff = h * NHD;
    const int qstart = qb << 7;

    uint32_t qhi[4][4], qlo[4][4];
    {
        const float* r0p = base + (size_t)(qstart + 16*w + g) * (3*NE) + qoff;
        const float* r1p = base + (size_t)(qstart + 16*w + g + 8) * (3*NE) + qoff;
#pragma unroll
        for (int kf = 0; kf < 4; kf++) {
            float2 v00 = *(const float2*)(r0p + 16*kf + 2*tig);
            float2 v10 = *(const float2*)(r1p + 16*kf + 2*tig);
            float2 v01 = *(const float2*)(r0p + 16*kf + 2*tig + 8);
            float2 v11 = *(const float2*)(r1p + 16*kf + 2*tig + 8);
            split_pack_bf16(v00.x*0.125f, v00.y*0.125f, qhi[kf][0], qlo[kf][0]);
            split_pack_bf16(v10.x*0.125f, v10.y*0.125f, qhi[kf][1], qlo[kf][1]);
            split_pack_bf16(v01.x*0.125f, v01.y*0.125f, qhi[kf][2], qlo[kf][2]);
            split_pack_bf16(v11.x*0.125f, v11.y*0.125f, qhi[kf][3], qlo[kf][3]);
        }
    }

    float o[8][4];
#pragma unroll
    for (int j = 0; j < 8; j++)
#pragma unroll
        for (int r = 0; r < 4; r++) o[j][r] = 0.f;
    float l0 = 0.f, l1 = 0.f;

    const int fr = tid >> 3;
    const int fc = (tid & 7) * 4;
    const int so = fr*36 + fc;
    const size_t gbase = (size_t)((b*4 + h)*1024) * 32;

    const int t8  = lane & 7;
    const int sel = lane >> 3;
    const uint32_t kfrag = (uint32_t)((((sel >> 1)*8 + t8)*36 + (sel & 1)*4) * 4);
    const uint32_t vfrag = (uint32_t)((((sel & 1)*8 + t8)*36 + (sel >> 1)*4) * 4);

    // preload tile 0 into buffer 0
    {
        const size_t go = gbase + (size_t)fr*32 + fc;
        *(uint4*)&sKhi[0][so] = *(const uint4*)&khi[go];
        *(uint4*)&sKlo[0][so] = *(const uint4*)&klo[go];
        *(uint4*)&sVhi[0][so] = *(const uint4*)&vhi[go];
        *(uint4*)&sVlo[0][so] = *(const uint4*)&vlo[go];
    }

    for (int kb = 0; kb < 32; kb++) {
        const int cur = kb & 1;
        __syncthreads();
        if (kb < 31) {
            const size_t go = gbase + (size_t)((kb+1)*32 + fr)*32 + fc;
            *(uint4*)&sKhi[1-cur][so] = *(const uint4*)&khi[go];
            *(uint4*)&sKlo[1-cur][so] = *(const uint4*)&klo[go];
            *(uint4*)&sVhi[1-cur][so] = *(const uint4*)&vhi[go];
            *(uint4*)&sVlo[1-cur][so] = *(const uint4*)&vlo[go];
        }
        const uint32_t sKhiB = cvta_s(sKhi[cur]), sKloB = cvta_s(sKlo[cur]);
        const uint32_t sVhiB = cvta_s(sVhi[cur]), sVloB = cvta_s(sVlo[cur]);

        // ---- S = Q K^T with split hi/err accumulators ----
        float s_hi[4][4], s_er[4][4];
#pragma unroll
        for (int j = 0; j < 4; j++)
#pragma unroll
            for (int r = 0; r < 4; r++) { s_hi[j][r] = 0.f; s_er[j][r] = 0.f; }
#pragma unroll
        for (int kf = 0; kf < 4; kf++) {
            uint32_t bh8[8], bl8[8];
            ldsm_x4(bh8 + 0, sKhiB + kfrag + kf*32);
            ldsm_x4(bh8 + 4, sKhiB + kfrag + 2304 + kf*32);
            ldsm_x4(bl8 + 0, sKloB + kfrag + kf*32);
            ldsm_x4(bl8 + 4, sKloB + kfrag + 2304 + kf*32);
#pragma unroll
            for (int j = 0; j < 4; j++) mma_bf16(s_hi[j], qhi[kf], bh8 + 2*j);
#pragma unroll
            for (int j = 0; j < 4; j++) mma_bf16(s_er[j], qhi[kf], bl8 + 2*j);
#pragma unroll
            for (int j = 0; j < 4; j++) mma_bf16(s_er[j], qlo[kf], bh8 + 2*j);
        }

        // ---- softmax weights p = exp(s) (no max shift) ----
        float p[4][4];
        float sum0 = 0.f, sum1 = 0.f;
#pragma unroll
        for (int j = 0; j < 4; j++) {
            p[j][0] = __expf(s_hi[j][0] + s_er[j][0]);
            p[j][1] = __expf(s_hi[j][1] + s_er[j][1]);
            p[j][2] = __expf(s_hi[j][2] + s_er[j][2]);
            p[j][3] = __expf(s_hi[j][3] + s_er[j][3]);
            sum0 += p[j][0] + p[j][1];
            sum1 += p[j][2] + p[j][3];
        }
        sum0 += __shfl_xor_sync(0xffffffffu, sum0, 1);
        sum0 += __shfl_xor_sync(0xffffffffu, sum0, 2);
        sum1 += __shfl_xor_sync(0xffffffffu, sum1, 1);
        sum1 += __shfl_xor_sync(0xffffffffu, sum1, 2);
        l0 += sum0;
        l1 += sum1;

        // ---- O += P V : P A-fragments built directly in registers ----
#pragma unroll
        for (int kf = 0; kf < 2; kf++) {
            uint32_t ph[4], pl[4];
            split_pack_bf16(p[2*kf  ][0], p[2*kf  ][1], ph[0], pl[0]);
            split_pack_bf16(p[2*kf  ][2], p[2*kf  ][3], ph[1], pl[1]);
            split_pack_bf16(p[2*kf+1][0], p[2*kf+1][1], ph[2], pl[2]);
            split_pack_bf16(p[2*kf+1][2], p[2*kf+1][3], ph[3], pl[3]);
#pragma unroll
            for (int j0 = 0; j0 < 8; j0 += 2) {
                uint32_t vh4[4], vl4[4];
                ldsm_x4_t(vh4, sVhiB + vfrag + kf*2304 + j0*16);
                ldsm_x4_t(vl4, sVloB + vfrag + kf*2304 + j0*16);
                mma_bf16(o[j0],   ph, vh4 + 0);
                mma_bf16(o[j0+1], ph, vh4 + 2);
                mma_bf16(o[j0],   ph, vl4 + 0);
                mma_bf16(o[j0+1], ph, vl4 + 2);
                mma_bf16(o[j0],   pl, vh4 + 0);
                mma_bf16(o[j0+1], pl, vh4 + 2);
            }
        }
    }

    const float inv0 = 1.f / l0, inv1 = 1.f / l1;
    float* c0 = ctx + ((size_t)(b*NT) + qstart + 16*w + g    ) * NE + h*NHD;
    float* c1 = ctx + ((size_t)(b*NT) + qstart + 16*w + g + 8) * NE + h*NHD;
#pragma unroll
    for (int j = 0; j < 8; j++) {
        *(float2*)(c0 + 8*j + 2*tig) = make_float2(o[j][0]*inv0, o[j][1]*inv0);
        *(float2*)(c1 + 8*j + 2*tig) = make_float2(o[j][2]*inv1, o[j][3]*inv1);
    }
}

// ============================================================================
// Boundary MLP: one warp per row, lane = hidden unit.
// ============================================================================
__global__ __launch_bounds__(256) void boundary_kernel(
    const float* __restrict__ ao, const float* __restrict__ w1,
    const float* __restrict__ b1, const float* __restrict__ w2,
    const float* __restrict__ b2, float* __restrict__ bscore)
{
    int row  = (blockIdx.x << 3) + (threadIdx.x >> 5);
    int lane = threadIdx.x & 31;
    const float4* a = (const float4*)(ao + (size_t)row * NE);
    const float4* w = (const float4*)(w1 + lane * NE);
    float acc = 0.f;
#pragma unroll 16
    for (int d = 0; d < 64; d++) {
        float4 av = a[d], wv = w[d];
        acc += av.x*wv.x + av.y*wv.y + av.z*wv.z + av.w*wv.w;
    }
    float hh = fmaxf(acc + b1[lane], 0.f);
    float s = hh * w2[lane];
#pragma unroll
    for (int off = 16; off; off >>= 1)
        s += __shfl_xor_sync(0xffffffffu, s, off);
    if (lane == 0)
        bscore[row] = 1.f / (1.f + expf(-(s + b2[0])));
}

// ============================================================================
// Per-batch inclusive cumsum (double) -> normalized -> patch ids.
// ============================================================================
__global__ __launch_bounds__(1024) void scan_kernel(
    const float* __restrict__ bscore, int* __restrict__ pid)
{
    __shared__ double sa[1024], sb[1024];
    int b = blockIdx.x, t = threadIdx.x;
    sa[t] = (double)bscore[b*NT + t];
    __syncthreads();
    double* src = sa; double* dst = sb;
#pragma unroll
    for (int off = 1; off < 1024; off <<= 1) {
        double v = src[t];
        if (t >= off) v += src[t - off];
        dst[t] = v;
        __syncthreads();
        double* tmp = src; src = dst; dst = tmp;
    }
    double total = src[1023] + 1e-6;
    double cbp = src[t] / total;
    int p = (int)floor(cbp * (double)NP);
    if (p > NP-1) p = NP-1;
    if (p < 0) p = 0;
    pid[b*NT + t] = p;
}

__device__ __forceinline__ int lower_bound_dev(const int* a, int n, int key) {
    int lo = 0, hi = n;
    while (lo < hi) { int mid = (lo + hi) >> 1; if (a[mid] < key) lo = mid + 1; else hi = mid; }
    return lo;
}

// ============================================================================
// Segment-mean pooling; pid monotone -> contiguous ranges, no atomics.
// ============================================================================
__global__ __launch_bounds__(256) void pool_kernel(
    const float* __restrict__ ao, const int* __restrict__ pid,
    float* __restrict__ pe)
{
    int bp = blockIdx.x;
    int b = bp >> 5, p = bp & 31;
    const int* pa = pid + b*NT;
    int s = lower_bound_dev(pa, NT, p);
    int e = lower_bound_dev(pa, NT, p+1);
    float inv = 1.f / (float)((e - s) > 0 ? (e - s) : 1);
    int col = threadIdx.x;
    float sum = 0.f;
    for (int t = s; t < e; t++)
        sum += ao[((size_t)(b*NT) + t) * NE + col];
    pe[(size_t)bp * NE + col] = sum * inv;
}

// ============================================================================
extern "C" void kernel_launch(void* const* d_in, const int* in_sizes, int n_in,
                              void* d_out, int out_size)
{
    (void)in_sizes; (void)n_in; (void)out_size;
    const float* x        = (const float*)d_in[0];
    const float* ip_w     = (const float*)d_in[1];
    const float* ip_b     = (const float*)d_in[2];
    const float* inproj_w = (const float*)d_in[3];
    const float* inproj_b = (const float*)d_in[4];
    const float* out_w    = (const float*)d_in[5];
    const float* out_b    = (const float*)d_in[6];
    const float* bp_w1    = (const float*)d_in[7];
    const float* bp_b1    = (const float*)d_in[8];
    const float* bp_w2    = (const float*)d_in[9];
    const float* bp_b2    = (const float*)d_in[10];
    const float* pr_w     = (const float*)d_in[11];
    const float* pr_b     = (const float*)d_in[12];
    float* out = (float*)d_out;

    void* p;
    float *qkv, *ctx, *ao, *bs, *pe, *wc, *bc; int* pid;
    uint32_t *khi, *klo, *vhi, *vlo;
    cudaGetSymbolAddress(&p, g_qkv); qkv = (float*)p;
    cudaGetSymbolAddress(&p, g_ctx); ctx = (float*)p;
    cudaGetSymbolAddress(&p, g_ao);  ao  = (float*)p;
    cudaGetSymbolAddress(&p, g_bs);  bs  = (float*)p;
    cudaGetSymbolAddress(&p, g_pid); pid = (int*)p;
    cudaGetSymbolAddress(&p, g_pe);  pe  = (float*)p;
    cudaGetSymbolAddress(&p, g_wc);  wc  = (float*)p;
    cudaGetSymbolAddress(&p, g_bc);  bc  = (float*)p;
    cudaGetSymbolAddress(&p, g_khi); khi = (uint32_t*)p;
    cudaGetSymbolAddress(&p, g_klo); klo = (uint32_t*)p;
    cudaGetSymbolAddress(&p, g_vhi); vhi = (uint32_t*)p;
    cudaGetSymbolAddress(&p, g_vlo); vlo = (uint32_t*)p;

    dim3 blk(256);
    // 0) fold ip into qkv
    fold_kernel<<<768, 32>>>(inproj_w, ip_w, ip_b, inproj_b, wc, bc);
    // 1) fused qkv projection (K=32)
    gemm_mma_kernel<<<dim3(3*NE/128, NM/128), blk>>>(x, wc, bc, qkv, 3*NE, 32);
    // 2) pre-split K/V
    presplit_kernel<<<4096, blk>>>(qkv, khi, klo, vhi, vlo);
    // 3) attention (BQ=128, double-buffered, 2 CTAs/SM forced)
    flash_mma_kernel<<<dim3(NT/128, NB*NH), blk>>>(qkv, khi, klo, vhi, vlo, ctx);
    // 4) out projection
    gemm_mma_kernel<<<dim3(NE/128, NM/128), blk>>>(ctx, out_w, out_b, ao, NE, NE);
    // 5) boundary scores
    boundary_kernel<<<NM/8, blk>>>(ao, bp_w1, bp_b1, bp_w2, bp_b2, bs);
    // 6) cumsum + patch ids
    scan_kernel<<<NB, NT>>>(bs, pid);
    // 7) segment-mean pooling
    pool_kernel<<<NB*NP, NE>>>(ao, pid, pe);
    // 8) patch projection
    gemm_mma_kernel<<<dim3(NE/128, (NB*NP)/128), blk>>>(pe, pr_w, pr_b, out, NE, NE);
}